// round 4
// baseline (speedup 1.0000x reference)
#include <cuda_runtime.h>
#include <cuda_bf16.h>
#include <cstdint>

#define B_ 32
#define C_ 256
#define H_ 32
#define W_ 32
#define K_ 1024
#define N_ 1024   /* hw positions per batch */
#define I_ 256    /* reduction dim */
#define ZELEMS (B_*C_*H_*W_)   /* 8388608 */
#define NPOS   (B_*N_)         /* 32768   */

#define EPS_CAND 0.012f
#define CMAX 16

// ---------------- scratch ----------------
__device__ float          g_zz[B_][I_][N_];     // 32 MB exact reinterpreted view [b][i][n]
__device__ __nv_bfloat16  g_zbT[B_][N_][I_];    // 16 MB bf16 transposed [b][n][i]
__device__ __nv_bfloat16  g_eb[K_][I_];         // 0.5 MB bf16 embedding
__device__ float          g_t[NPOS];
__device__ float          g_s[K_];
__device__ unsigned short g_cand[NPOS*8*CMAX];
__device__ int            g_ccnt[NPOS*8];
__device__ int            g_idx[NPOS];
__device__ double         g_lacc;

__device__ __forceinline__ uint32_t smem_u32(const void* p) {
    uint32_t a;
    asm("{ .reg .u64 t; cvta.to.shared.u64 t, %1; cvt.u32.u64 %0, t; }" : "=r"(a) : "l"(p));
    return a;
}

__global__ void k_init() { g_lacc = 0.0; }

// ---------------- transpose: z -> g_zz (exact fp32 view) + g_zbT (bf16 [b][n][i]) ----------------
// zz[b,i,n] = z[b, n&255, i>>3, 4*(i&7)+(n>>8)]
__global__ __launch_bounds__(256) void k_transpose(const float* __restrict__ z) {
    __shared__ float tile[64][33];
    int c0 = blockIdx.x * 64;
    int h  = blockIdx.y;
    int b  = blockIdx.z;
    int t  = threadIdx.x;
    for (int e = t; e < 2048; e += 256) {
        int row = e >> 5, w = e & 31;
        tile[row][w] = z[(((b*C_) + c0 + row)*H_ + h)*W_ + w];
    }
    __syncthreads();
    for (int e = t; e < 2048; e += 256) {
        int cc = e & 63, chunk = e >> 6;
        int il = chunk >> 2, q = chunk & 3;
        g_zz[b][h*8 + il][q*256 + c0 + cc] = tile[cc][il*4 + q];
    }
    // fused bf16 transposed view: g_zbT[b][n][i], n = q*256 + c0 + c, i = h*8 + il
    {
        int c = t >> 2, q = t & 3;
        union { __nv_bfloat162 h2[4]; uint4 u; } pk;
        #pragma unroll
        for (int p = 0; p < 4; ++p) {
            float v0 = tile[c][(2*p  )*4 + q];
            float v1 = tile[c][(2*p+1)*4 + q];
            pk.h2[p] = __nv_bfloat162(__float2bfloat16_rn(v0), __float2bfloat16_rn(v1));
        }
        *(uint4*)&g_zbT[b][q*256 + c0 + c][h*8] = pk.u;
    }
}

__global__ __launch_bounds__(256) void k_ebf16(const float* __restrict__ emb) {
    int i = blockIdx.x*256 + threadIdx.x;
    ((__nv_bfloat16*)g_eb)[i] = __float2bfloat16_rn(emb[i]);
}

__global__ __launch_bounds__(256) void k_tn() {
    int gn = blockIdx.x*blockDim.x + threadIdx.x;
    if (gn >= NPOS) return;
    int b = gn >> 10, n = gn & 1023;
    float acc = 0.f;
    for (int i = 0; i < I_; ++i) {
        float v = g_zz[b][i][n];
        acc = __fadd_rn(acc, __fmul_rn(v, v));
    }
    g_t[gn] = acc;
}

__global__ __launch_bounds__(256) void k_sk(const float* __restrict__ emb) {
    __shared__ float sm[64*257];
    int k0 = blockIdx.x*64;
    int t = threadIdx.x;
    for (int j = 0; j < 64; ++j)
        sm[j*257 + t] = emb[(k0+j)*256 + t];
    __syncthreads();
    if (t < 64) {
        float acc = 0.f;
        for (int c = 0; c < 256; ++c) {
            float v = sm[t*257 + c];
            acc = __fadd_rn(acc, __fmul_rn(v, v));
        }
        g_s[k0 + t] = acc;
    }
}

// ---------------- mma.sync bf16 GEMM + candidate collection ----------------
// grid (nb=8, kb=8, b=32), 256 thr (8 warps). CTA tile: M=128 codes x N=128 pos x K=256.
// Warp tile 64x32: 4 m16 x 4 n8 x 16 ksteps of k16.
// smem rows are 512B (256 bf16); 16B chunks XOR-swizzled by (row&7)*16 -> conflict-free ldmatrix.
#define SM_S   0
#define SM_A   1024
#define SM_B   (1024 + 65536)
#define SM_TOT (1024 + 65536 + 65536)
#define PITCH  132

__global__ __launch_bounds__(256, 1) void k_mma() {
    extern __shared__ char sm[];
    uint32_t sb = smem_u32(sm);
    int t = threadIdx.x, warp = t >> 5, lane = t & 31;
    int nb = blockIdx.x, kb = blockIdx.y, b = blockIdx.z;
    int n0 = nb*128, k0 = kb*128;

    if (t < 128) ((float*)(sm + SM_S))[t] = g_s[k0 + t];

    // stage A (codes) and B (positions): 128 rows x 512B each
    const uint4* pA = (const uint4*)g_eb;
    const uint4* pB = (const uint4*)g_zbT;
    #pragma unroll
    for (int j = 0; j < 16; ++j) {
        int e = j*256 + t;
        int row = e >> 5, q = e & 31;                       // q: 16B chunk within row
        uint32_t off = (uint32_t)row*512u + ((uint32_t)(q*16) ^ (uint32_t)((row & 7)*16));
        *(uint4*)(sm + SM_A + off) = pA[(k0 + row)*32 + q];
        *(uint4*)(sm + SM_B + off) = pB[((b << 10) + n0 + row)*32 + q];
    }
    __syncthreads();

    int wm = warp >> 2, wn = warp & 3;
    int mbase = wm*64, nbase = wn*32;

    float acc[4][4][4];
    #pragma unroll
    for (int mi = 0; mi < 4; ++mi)
        #pragma unroll
        for (int ni = 0; ni < 4; ++ni)
            #pragma unroll
            for (int r = 0; r < 4; ++r) acc[mi][ni][r] = 0.f;

    int lr = lane & 15;
    int lx = (lane >> 4) * 16;
    uint32_t aAddr[4], aSw[4], bAddr[2], bSw[2];
    #pragma unroll
    for (int mi = 0; mi < 4; ++mi) {
        int r = mbase + mi*16 + lr;
        aAddr[mi] = sb + SM_A + (uint32_t)r*512u;
        aSw[mi]   = (uint32_t)((r & 7)*16);
    }
    #pragma unroll
    for (int nh = 0; nh < 2; ++nh) {
        int r = nbase + nh*16 + lr;
        bAddr[nh] = sb + SM_B + (uint32_t)r*512u;
        bSw[nh]   = (uint32_t)((r & 7)*16);
    }

    #pragma unroll
    for (int ks = 0; ks < 16; ++ks) {
        uint32_t x = (uint32_t)(ks*32 + lx);
        uint32_t af[4][4];
        #pragma unroll
        for (int mi = 0; mi < 4; ++mi) {
            uint32_t ad = aAddr[mi] + (x ^ aSw[mi]);
            asm volatile("ldmatrix.sync.aligned.m8n8.x4.shared.b16 {%0,%1,%2,%3}, [%4];"
                : "=r"(af[mi][0]), "=r"(af[mi][1]), "=r"(af[mi][2]), "=r"(af[mi][3]) : "r"(ad));
        }
        uint32_t bf[2][4];
        #pragma unroll
        for (int nh = 0; nh < 2; ++nh) {
            uint32_t ad = bAddr[nh] + (x ^ bSw[nh]);
            asm volatile("ldmatrix.sync.aligned.m8n8.x4.shared.b16 {%0,%1,%2,%3}, [%4];"
                : "=r"(bf[nh][0]), "=r"(bf[nh][1]), "=r"(bf[nh][2]), "=r"(bf[nh][3]) : "r"(ad));
        }
        #pragma unroll
        for (int mi = 0; mi < 4; ++mi)
            #pragma unroll
            for (int ni = 0; ni < 4; ++ni) {
                int nh = ni >> 1, sel = ni & 1;
                uint32_t b0 = bf[nh][sel];      // k 0-7
                uint32_t b1 = bf[nh][sel + 2];  // k 8-15
                asm volatile("mma.sync.aligned.m16n8k16.row.col.f32.bf16.bf16.f32 "
                    "{%0,%1,%2,%3}, {%4,%5,%6,%7}, {%8,%9}, {%0,%1,%2,%3};"
                    : "+f"(acc[mi][ni][0]), "+f"(acc[mi][ni][1]),
                      "+f"(acc[mi][ni][2]), "+f"(acc[mi][ni][3])
                    : "r"(af[mi][0]), "r"(af[mi][1]), "r"(af[mi][2]), "r"(af[mi][3]),
                      "r"(b0), "r"(b1));
            }
    }
    __syncthreads();

    // epilogue: dump dots to smem D[k][n] (pitch 132), overlapping A/B staging
    float* Ds = (float*)(sm + SM_A);
    int g = lane >> 2, tq = lane & 3;
    #pragma unroll
    for (int mi = 0; mi < 4; ++mi) {
        int m0 = mbase + mi*16 + g;
        #pragma unroll
        for (int ni = 0; ni < 4; ++ni) {
            int n = nbase + ni*8 + 2*tq;
            *(float2*)&Ds[m0*PITCH + n]       = make_float2(acc[mi][ni][0], acc[mi][ni][1]);
            *(float2*)&Ds[(m0 + 8)*PITCH + n] = make_float2(acc[mi][ni][2], acc[mi][ni][3]);
        }
    }
    __syncthreads();

    // per-position tile-min + candidate collection
    if (t < 128) {
        const float* S = (const float*)(sm + SM_S);
        int gn = b*1024 + n0 + t;
        float tn = g_t[gn];
        float mn = __int_as_float(0x7f800000);
        for (int k = 0; k < 128; ++k) {
            float d = S[k] + tn - 2.0f*Ds[k*PITCH + t];
            mn = fminf(mn, d);
        }
        float thr = mn + EPS_CAND;
        int cnt = 0;
        unsigned short loc[CMAX];
        for (int k = 0; k < 128; ++k) {
            float d = S[k] + tn - 2.0f*Ds[k*PITCH + t];
            if (d <= thr) {
                if (cnt < CMAX) loc[cnt] = (unsigned short)(k0 + k);
                cnt++;
            }
        }
        g_ccnt[gn*8 + kb] = cnt;
        int nw = cnt < CMAX ? cnt : CMAX;
        for (int c = 0; c < nw; ++c)
            g_cand[(gn*8 + kb)*CMAX + c] = loc[c];
    }
}

// ---------------- exact recheck (bitwise-identical to round-1 selection) ----------------
__global__ __launch_bounds__(128) void k_recheck(const float* __restrict__ emb,
                                                 float* __restrict__ out, int out_size) {
    int gn = blockIdx.x*128 + threadIdx.x;
    int b = gn >> 10, n = gn & 1023;
    float tn = g_t[gn];

    unsigned short list[8*CMAX];
    int total = 0;
    bool ovf = false;
    for (int kb = 0; kb < 8; ++kb) {
        int c = g_ccnt[gn*8 + kb];
        if (c > CMAX) { ovf = true; continue; }
        for (int j = 0; j < c; ++j)
            list[total++] = g_cand[(gn*8 + kb)*CMAX + j];
    }

    float best = __int_as_float(0x7f800000);
    int bi = 0x7fffffff;
    if (!ovf) {
        for (int c = 0; c < total; ++c) {
            int k = list[c];
            const float* e = emb + k*256;
            float acc = 0.f;
            for (int i = 0; i < I_; ++i)
                acc = fmaf(e[i], g_zz[b][i][n], acc);
            float d = __fsub_rn(__fadd_rn(g_s[k], tn), __fmul_rn(2.0f, acc));
            if (d < best || (d == best && k < bi)) { best = d; bi = k; }
        }
    } else {
        for (int k = 0; k < K_; ++k) {
            const float* e = emb + k*256;
            float acc = 0.f;
            for (int i = 0; i < I_; ++i)
                acc = fmaf(e[i], g_zz[b][i][n], acc);
            float d = __fsub_rn(__fadd_rn(g_s[k], tn), __fmul_rn(2.0f, acc));
            if (d < best) { best = d; bi = k; }
        }
    }
    g_idx[gn] = bi;
    if (out_size >= ZELEMS + NPOS)      out[ZELEMS + gn] = (float)bi;
    else if (out_size == NPOS)          out[gn]          = (float)bi;
}

// ---------------- writeout + loss ----------------
__global__ __launch_bounds__(256) void k_writeout(const float* __restrict__ z,
                                                  const float* __restrict__ emb,
                                                  float* __restrict__ out, int out_size) {
    int o = blockIdx.x*256 + threadIdx.x;
    double local = 0.0;
    if (o < ZELEMS) {
        int w = o & 31, h = (o >> 5) & 31, c = (o >> 10) & 255, b = o >> 18;
        int n = h*32 + w;
        int kidx = g_idx[b*1024 + n];
        float zq = emb[kidx*256 + c];
        float zp = z[o];
        float diff = __fsub_rn(zq, zp);
        if (out_size >= ZELEMS) out[o] = __fadd_rn(zp, diff);
        float sq = __fmul_rn(diff, diff);
        local = (double)sq;
    }
    __shared__ double sd[256];
    sd[threadIdx.x] = local;
    __syncthreads();
    for (int s = 128; s > 0; s >>= 1) {
        if (threadIdx.x < s) sd[threadIdx.x] += sd[threadIdx.x + s];
        __syncthreads();
    }
    if (threadIdx.x == 0) atomicAdd(&g_lacc, sd[0]);
}

__global__ void k_finalize(float* __restrict__ out, int out_size) {
    float m = (float)(g_lacc / (double)ZELEMS);
    float loss = __fadd_rn(m, __fmul_rn(0.25f, m));
    if (out_size >= ZELEMS + NPOS + 1)  out[ZELEMS + NPOS] = loss;
    else if (out_size == ZELEMS + 1)    out[ZELEMS]        = loss;
    else if (out_size == 1)             out[0]             = loss;
}

// ---------------- launch ----------------
extern "C" void kernel_launch(void* const* d_in, const int* in_sizes, int n_in,
                              void* d_out, int out_size) {
    const float* z   = (const float*)d_in[0];
    const float* emb = (const float*)d_in[1];
    if (n_in >= 2 && in_sizes[0] == K_*C_ && in_sizes[1] == ZELEMS) {
        z = (const float*)d_in[1]; emb = (const float*)d_in[0];
    }
    float* out = (float*)d_out;

    cudaFuncSetAttribute(k_mma, cudaFuncAttributeMaxDynamicSharedMemorySize, SM_TOT);

    k_init<<<1, 1>>>();
    k_transpose<<<dim3(4, 32, 32), 256>>>(z);
    k_ebf16<<<K_*C_/256, 256>>>(emb);
    k_tn<<<NPOS/256, 256>>>();
    k_sk<<<K_/64, 256>>>(emb);
    k_mma<<<dim3(8, 8, 32), 256, SM_TOT>>>();
    k_recheck<<<NPOS/128, 128>>>(emb, out, out_size);
    k_writeout<<<ZELEMS/256, 256>>>(z, emb, out, out_size);
    k_finalize<<<1, 1>>>(out, out_size);
}

// round 5
// speedup vs baseline: 19.1964x; 19.1964x over previous
#include <cuda_runtime.h>
#include <cstdint>

#define B_ 32
#define C_ 256
#define H_ 32
#define W_ 32
#define K_ 1024
#define N_ 1024
#define I_ 256
#define ZELEMS (B_*C_*H_*W_)   /* 8388608 */
#define NPOS   (B_*N_)         /* 32768   */

// ---------------- scratch ----------------
__device__ float  g_zz[B_][I_][N_];   // 32 MB exact reinterpreted view [b][i][n]
__device__ float  g_ebT[I_][2*K_];    // 2 MB: g_ebT[i][2k]=g_ebT[i][2k+1]=emb[k][i]
__device__ float  g_t[NPOS];
__device__ float  g_s[K_];
__device__ float  g_pmin[NPOS*8];
__device__ int    g_pidx[NPOS*8];
__device__ int    g_idx[NPOS];
__device__ double g_lacc;

__global__ void k_init() { g_lacc = 0.0; }

// zz[b,i,n] = z[b, n&255, i>>3, 4*(i&7)+(n>>8)]  (the reshape-reinterpretation)
__global__ __launch_bounds__(256) void k_transpose(const float* __restrict__ z) {
    __shared__ float tile[64][33];
    int c0 = blockIdx.x * 64;
    int h  = blockIdx.y;
    int b  = blockIdx.z;
    int t  = threadIdx.x;
    for (int e = t; e < 2048; e += 256) {
        int row = e >> 5, w = e & 31;
        tile[row][w] = z[(((b*C_) + c0 + row)*H_ + h)*W_ + w];
    }
    __syncthreads();
    for (int e = t; e < 2048; e += 256) {
        int cc = e & 63, chunk = e >> 6;
        int il = chunk >> 2, q = chunk & 3;
        g_zz[b][h*8 + il][q*256 + c0 + cc] = tile[cc][il*4 + q];
    }
}

// duplicated transposed embedding for FFMA2 operand pairs
__global__ __launch_bounds__(256) void k_ebT(const float* __restrict__ emb) {
    int gid = blockIdx.x*256 + threadIdx.x;      // gid = i*1024 + k
    int i = gid >> 10, k = gid & 1023;
    float v = emb[k*256 + i];
    *(float2*)&g_ebT[i][2*k] = make_float2(v, v);
}

__global__ __launch_bounds__(256) void k_tn() {
    int gn = blockIdx.x*blockDim.x + threadIdx.x;
    if (gn >= NPOS) return;
    int b = gn >> 10, n = gn & 1023;
    float acc = 0.f;
    for (int i = 0; i < I_; ++i) {
        float v = g_zz[b][i][n];
        acc = __fadd_rn(acc, __fmul_rn(v, v));
    }
    g_t[gn] = acc;
}

__global__ __launch_bounds__(256) void k_sk(const float* __restrict__ emb) {
    __shared__ float sm[64*257];
    int k0 = blockIdx.x*64;
    int t = threadIdx.x;
    for (int j = 0; j < 64; ++j)
        sm[j*257 + t] = emb[(k0+j)*256 + t];
    __syncthreads();
    if (t < 64) {
        float acc = 0.f;
        for (int c = 0; c < 256; ++c) {
            float v = sm[t*257 + c];
            acc = __fadd_rn(acc, __fmul_rn(v, v));
        }
        g_s[k0 + t] = acc;
    }
}

// ---------------- FFMA2 (f32x2) exact GEMM + fused dist/argmin ----------------
// grid (nb=8, kb=8, b=32), 256 threads. Tile 128k x 128n x 256i, panels of 32 i.
// Es rows hold 128 k-values DUPLICATED (256 floats) -> {a,a} pairs via LDS.128.
#define EPITCH 264
#define ZPITCH 132
#define SM_ES  0
#define SM_ZS  (32*EPITCH*4)
#define SM_TOT (32*EPITCH*4 + 32*ZPITCH*4)

__device__ __forceinline__ unsigned long long ffma2(unsigned long long a,
                                                    unsigned long long b,
                                                    unsigned long long c) {
    unsigned long long d;
    asm("fma.rn.f32x2 %0, %1, %2, %3;" : "=l"(d) : "l"(a), "l"(b), "l"(c));
    return d;
}

__global__ __launch_bounds__(256, 2) void k_gemm() {
    extern __shared__ char smraw[];
    float* Es = (float*)(smraw + SM_ES);
    float* Zs = (float*)(smraw + SM_ZS);
    int nb = blockIdx.x, kb = blockIdx.y, b = blockIdx.z;
    int n0 = nb*128, k0 = kb*128;
    int t = threadIdx.x;
    int tx = t & 15, ty = t >> 4;

    unsigned long long acc2[8][4];
    #pragma unroll
    for (int r = 0; r < 8; ++r)
        #pragma unroll
        for (int cp = 0; cp < 4; ++cp) acc2[r][cp] = 0ull;

    for (int it = 0; it < 8; ++it) {
        __syncthreads();
        // stage Es: 32 rows x 256 floats (dup'd), coalesced from g_ebT
        #pragma unroll
        for (int j = 0; j < 8; ++j) {
            int e = j*256 + t;                    // float4 units
            int ii = e >> 6, colu = e & 63;
            *(float4*)&Es[ii*EPITCH + colu*4] =
                *(const float4*)&g_ebT[it*32 + ii][2*k0 + colu*4];
        }
        // stage Zs: 32 rows x 128 floats
        #pragma unroll
        for (int j = 0; j < 4; ++j) {
            int e = j*256 + t;
            int ii = e >> 5, colu = e & 31;
            *(float4*)&Zs[ii*ZPITCH + colu*4] =
                *(const float4*)&g_zz[b][it*32 + ii][n0 + colu*4];
        }
        __syncthreads();
        #pragma unroll
        for (int ii = 0; ii < 32; ++ii) {
            const float* er = &Es[ii*EPITCH + ty*16];
            const float* zr = &Zs[ii*ZPITCH + tx*8];
            ulonglong2 ea0 = *(const ulonglong2*)(er);      // {E0,E0},{E1,E1}
            ulonglong2 ea1 = *(const ulonglong2*)(er + 4);  // {E2,E2},{E3,E3}
            ulonglong2 ea2 = *(const ulonglong2*)(er + 8);
            ulonglong2 ea3 = *(const ulonglong2*)(er + 12);
            ulonglong2 zb0 = *(const ulonglong2*)(zr);      // {n0,n1},{n2,n3}
            ulonglong2 zb1 = *(const ulonglong2*)(zr + 4);  // {n4,n5},{n6,n7}
            unsigned long long av[8] = {ea0.x, ea0.y, ea1.x, ea1.y,
                                        ea2.x, ea2.y, ea3.x, ea3.y};
            unsigned long long bv[4] = {zb0.x, zb0.y, zb1.x, zb1.y};
            #pragma unroll
            for (int r = 0; r < 8; ++r)
                #pragma unroll
                for (int cp = 0; cp < 4; ++cp)
                    acc2[r][cp] = ffma2(av[r], bv[cp], acc2[r][cp]);
        }
    }

    // unpack: acc[r][c], c = 2*cp + h  -> identical dist/argmin as round-1
    float acc[8][8];
    #pragma unroll
    for (int r = 0; r < 8; ++r)
        #pragma unroll
        for (int cp = 0; cp < 4; ++cp) {
            float lo, hi;
            asm("mov.b64 {%0,%1}, %2;" : "=f"(lo), "=f"(hi) : "l"(acc2[r][cp]));
            acc[r][2*cp]   = lo;
            acc[r][2*cp+1] = hi;
        }

    float sv[8], tv[8];
    #pragma unroll
    for (int r = 0; r < 8; ++r) sv[r] = g_s[k0 + ty*8 + r];
    #pragma unroll
    for (int c = 0; c < 8; ++c) tv[c] = g_t[b*1024 + n0 + tx*8 + c];

    float mv[8]; int mi[8];
    #pragma unroll
    for (int c = 0; c < 8; ++c) {
        float d0 = __fsub_rn(__fadd_rn(sv[0], tv[c]), __fmul_rn(2.0f, acc[0][c]));
        mv[c] = d0; mi[c] = k0 + ty*8;
        #pragma unroll
        for (int r = 1; r < 8; ++r) {
            float d = __fsub_rn(__fadd_rn(sv[r], tv[c]), __fmul_rn(2.0f, acc[r][c]));
            if (d < mv[c]) { mv[c] = d; mi[c] = k0 + ty*8 + r; }
        }
    }

    __syncthreads();
    float* red  = (float*)Es;
    int*   ridx = (int*)Zs;
    #pragma unroll
    for (int c = 0; c < 8; ++c) {
        red [ty*128 + tx*8 + c] = mv[c];
        ridx[ty*128 + tx*8 + c] = mi[c];
    }
    __syncthreads();
    if (t < 128) {
        float best = red[t]; int bi = ridx[t];
        for (int y = 1; y < 16; ++y) {
            float d = red[y*128 + t]; int ix = ridx[y*128 + t];
            if (d < best || (d == best && ix < bi)) { best = d; bi = ix; }
        }
        int gn = b*1024 + n0 + t;
        g_pmin[gn*8 + kb] = best;
        g_pidx[gn*8 + kb] = bi;
    }
}

__global__ __launch_bounds__(256) void k_combine(float* __restrict__ out, int out_size) {
    int gn = blockIdx.x*blockDim.x + threadIdx.x;
    if (gn >= NPOS) return;
    float best = g_pmin[gn*8]; int bi = g_pidx[gn*8];
    for (int kb = 1; kb < 8; ++kb) {
        float d = g_pmin[gn*8 + kb]; int ix = g_pidx[gn*8 + kb];
        if (d < best || (d == best && ix < bi)) { best = d; bi = ix; }
    }
    g_idx[gn] = bi;
    if (out_size >= ZELEMS + NPOS)      out[ZELEMS + gn] = (float)bi;
    else if (out_size == NPOS)          out[gn]          = (float)bi;
}

// out = fl(z_p + fl(z_q - z_p)); loss sum of fl(diff^2) in double. 4 elems/thread.
__global__ __launch_bounds__(256) void k_writeout(const float* __restrict__ z,
                                                  const float* __restrict__ emb,
                                                  float* __restrict__ out, int out_size) {
    int o4 = blockIdx.x*256 + threadIdx.x;       // float4 index
    double local = 0.0;
    if (o4*4 < ZELEMS) {
        int o = o4*4;
        int w = o & 31, h = (o >> 5) & 31, c = (o >> 10) & 255, b = o >> 18;
        float4 zp4 = *(const float4*)&z[o];
        float r[4];
        float zp[4] = {zp4.x, zp4.y, zp4.z, zp4.w};
        #pragma unroll
        for (int j = 0; j < 4; ++j) {
            int n = h*32 + (w + j);
            int kidx = g_idx[b*1024 + n];
            float zq = emb[kidx*256 + c];
            float diff = __fsub_rn(zq, zp[j]);
            r[j] = __fadd_rn(zp[j], diff);
            float sq = __fmul_rn(diff, diff);
            local += (double)sq;
        }
        if (out_size >= ZELEMS) *(float4*)&out[o] = make_float4(r[0], r[1], r[2], r[3]);
    }
    __shared__ double sd[256];
    sd[threadIdx.x] = local;
    __syncthreads();
    for (int s = 128; s > 0; s >>= 1) {
        if (threadIdx.x < s) sd[threadIdx.x] += sd[threadIdx.x + s];
        __syncthreads();
    }
    if (threadIdx.x == 0) atomicAdd(&g_lacc, sd[0]);
}

__global__ void k_finalize(float* __restrict__ out, int out_size) {
    float m = (float)(g_lacc / (double)ZELEMS);
    float loss = __fadd_rn(m, __fmul_rn(0.25f, m));
    if (out_size >= ZELEMS + NPOS + 1)  out[ZELEMS + NPOS] = loss;
    else if (out_size == ZELEMS + 1)    out[ZELEMS]        = loss;
    else if (out_size == 1)             out[0]             = loss;
}

extern "C" void kernel_launch(void* const* d_in, const int* in_sizes, int n_in,
                              void* d_out, int out_size) {
    const float* z   = (const float*)d_in[0];
    const float* emb = (const float*)d_in[1];
    if (n_in >= 2 && in_sizes[0] == K_*C_ && in_sizes[1] == ZELEMS) {
        z = (const float*)d_in[1]; emb = (const float*)d_in[0];
    }
    float* out = (float*)d_out;

    cudaFuncSetAttribute(k_gemm, cudaFuncAttributeMaxDynamicSharedMemorySize, SM_TOT);

    k_init<<<1, 1>>>();
    k_transpose<<<dim3(4, 32, 32), 256>>>(z);
    k_ebT<<<I_*K_/256, 256>>>(emb);
    k_tn<<<NPOS/256, 256>>>();
    k_sk<<<K_/64, 256>>>(emb);
    k_gemm<<<dim3(8, 8, 32), 256, SM_TOT>>>();
    k_combine<<<NPOS/256, 256>>>(out, out_size);
    k_writeout<<<ZELEMS/4/256, 256>>>(z, emb, out, out_size);
    k_finalize<<<1, 1>>>(out, out_size);
}